// round 1
// baseline (speedup 1.0000x reference)
#include <cuda_runtime.h>

// Problem constants (fixed by the reference)
#define NN    100000   // entities
#define DH    300      // e_hidden
#define EAll  800000   // symmetric all-edge count (2*EH)
#define EKG   400000   // KG1 triples
#define RR    2000     // relations
#define RHID  100      // r_hidden
#define NLGE  60000    // line-graph edges
#define OSTR  800      // output row stride

// ------------------------- scratch (static, allocation-free) -------------------------
__device__ float    g_A[(size_t)NN*DH];
__device__ float    g_B[(size_t)NN*DH];
__device__ float    g_C[(size_t)NN*DH];
__device__ float    g_deg[NN];
__device__ float    g_dinv[NN];
__device__ float    g_s1[NN];
__device__ float    g_s2[NN];
__device__ unsigned g_umax[NN];
__device__ float    g_sum[NN];
__device__ float    g_eE[EAll];
__device__ float    g_eP[EAll];

__device__ float    g_rm[RR*RHID];
__device__ float    g_rt[RR*RHID];
__device__ float    g_xr[RR*RHID];
__device__ float    g_rg[RR*RHID];
__device__ float    g_lv1[NLGE];
__device__ float    g_lv2[NLGE];
__device__ float    g_lw[NLGE];
__device__ unsigned g_rumax[RR];
__device__ float    g_rsum[RR];
__device__ float    g_srcat[RR];
__device__ float    g_tr[RR];

// Order-preserving float <-> uint mapping (for atomicMax on floats incl. negatives)
__device__ __forceinline__ unsigned f2o(float f){
    unsigned u = __float_as_uint(f);
    return (u & 0x80000000u) ? ~u : (u | 0x80000000u);
}
__device__ __forceinline__ float o2f(unsigned u){
    return (u & 0x80000000u) ? __uint_as_float(u & 0x7fffffffu) : __uint_as_float(~u);
}

// ------------------------- GEMM: C[M,N] = A[M,K] * B[N,K]^T (both K-major) -------------------------
__global__ __launch_bounds__(256) void sgemm_nt(
    const float* __restrict__ A, const float* __restrict__ B,
    float* __restrict__ C, int M, int N, int K)
{
    __shared__ float As[8][128];
    __shared__ float Bs[8][128];
    int bm = blockIdx.y * 128;
    int bn = blockIdx.x * 128;
    int tid = threadIdx.x;
    int tx = tid & 15;
    int ty = tid >> 4;
    int lrow = tid >> 1;          // 0..127
    int lcol = (tid & 1) * 4;     // 0 or 4

    float acc[8][8];
    #pragma unroll
    for (int i = 0; i < 8; i++)
        #pragma unroll
        for (int j = 0; j < 8; j++) acc[i][j] = 0.f;

    for (int k0 = 0; k0 < K; k0 += 8) {
        float4 av = make_float4(0.f,0.f,0.f,0.f);
        float4 bv = make_float4(0.f,0.f,0.f,0.f);
        int gk = k0 + lcol;
        int ar = bm + lrow;
        if (ar < M) {
            if (gk + 4 <= K) av = *reinterpret_cast<const float4*>(A + (size_t)ar*K + gk);
            else {
                float* p = reinterpret_cast<float*>(&av);
                for (int u = 0; u < 4; u++) if (gk + u < K) p[u] = A[(size_t)ar*K + gk + u];
            }
        }
        int br = bn + lrow;
        if (br < N) {
            if (gk + 4 <= K) bv = *reinterpret_cast<const float4*>(B + (size_t)br*K + gk);
            else {
                float* p = reinterpret_cast<float*>(&bv);
                for (int u = 0; u < 4; u++) if (gk + u < K) p[u] = B[(size_t)br*K + gk + u];
            }
        }
        As[lcol+0][lrow]=av.x; As[lcol+1][lrow]=av.y; As[lcol+2][lrow]=av.z; As[lcol+3][lrow]=av.w;
        Bs[lcol+0][lrow]=bv.x; Bs[lcol+1][lrow]=bv.y; Bs[lcol+2][lrow]=bv.z; Bs[lcol+3][lrow]=bv.w;
        __syncthreads();
        #pragma unroll
        for (int kk = 0; kk < 8; kk++) {
            float a[8], b[8];
            #pragma unroll
            for (int i = 0; i < 8; i++) a[i] = As[kk][ty*8+i];
            #pragma unroll
            for (int j = 0; j < 8; j++) b[j] = Bs[kk][tx*8+j];
            #pragma unroll
            for (int i = 0; i < 8; i++)
                #pragma unroll
                for (int j = 0; j < 8; j++) acc[i][j] = fmaf(a[i], b[j], acc[i][j]);
        }
        __syncthreads();
    }
    #pragma unroll
    for (int i = 0; i < 8; i++) {
        int r = bm + ty*8 + i;
        if (r >= M) continue;
        #pragma unroll
        for (int j = 0; j < 8; j++) {
            int c = bn + tx*8 + j;
            if (c < N) C[(size_t)r*N + c] = acc[i][j];
        }
    }
}

// ------------------------- elementwise / graph kernels -------------------------
__global__ void k_fill_u32(unsigned* p, unsigned v, int n){
    int i = blockIdx.x*blockDim.x + threadIdx.x;
    if (i < n) p[i] = v;
}
__global__ void k_deg(const int* __restrict__ idx, float* __restrict__ deg, int E){
    int i = blockIdx.x*blockDim.x + threadIdx.x;
    if (i < E) atomicAdd(&deg[idx[i]], 1.f);
}
__global__ void k_dinv(const float* __restrict__ deg, float* __restrict__ dinv, int n){
    int i = blockIdx.x*blockDim.x + threadIdx.x;
    if (i < n){ float d = deg[i]; dinv[i] = d > 0.f ? rsqrtf(d) : 0.f; }
}
// GCN scatter: out[i] += dinv[j]*dinv[i] * xw[j], warp per edge
__global__ void k_gcn_scatter(const float* __restrict__ xw, const int* __restrict__ ej,
    const int* __restrict__ ei, const float* __restrict__ dinv,
    float* __restrict__ out, int E)
{
    int w = (blockIdx.x*blockDim.x + threadIdx.x) >> 5;
    if (w >= E) return;
    int lane = threadIdx.x & 31;
    int j = __ldg(&ej[w]), i = __ldg(&ei[w]);
    float nrm = dinv[j] * dinv[i];
    const float* src = xw + (size_t)j*DH;
    float* dst = out + (size_t)i*DH;
    for (int d = lane; d < DH; d += 32) atomicAdd(&dst[d], nrm * src[d]);
}
// highway: out = g*relu(sc) + (1-g)*x, g = sigmoid(G + b)
__global__ void k_highway(const float* __restrict__ x, const float* __restrict__ sc,
    const float* __restrict__ G, const float* __restrict__ b,
    float* __restrict__ out, int n, int d, int ostride)
{
    int idx = blockIdx.x*blockDim.x + threadIdx.x;
    if (idx >= n*d) return;
    int r = idx / d, c = idx - r*d;
    float x2 = fmaxf(sc[idx], 0.f);
    float g = 1.f / (1.f + expf(-(G[idx] + b[c])));
    out[(size_t)r*ostride + c] = g*x2 + (1.f - g)*x[idx];
}
// per-row dual dot products (warp per row); s2 may be null
__global__ void k_dot2(const float* __restrict__ x, int ld, int d,
    const float* __restrict__ a1, const float* __restrict__ a2,
    float* __restrict__ s1, float* __restrict__ s2, int n)
{
    int w = (blockIdx.x*blockDim.x + threadIdx.x) >> 5;
    if (w >= n) return;
    int lane = threadIdx.x & 31;
    const float* row = x + (size_t)w*ld;
    float u = 0.f, v = 0.f;
    for (int c = lane; c < d; c += 32){ float xv = row[c]; u += xv*a1[c]; v += xv*a2[c]; }
    #pragma unroll
    for (int o = 16; o; o >>= 1){
        u += __shfl_down_sync(0xffffffffu, u, o);
        v += __shfl_down_sync(0xffffffffu, v, o);
    }
    if (lane == 0){ s1[w] = u; if (s2) s2[w] = v; }
}
// s_rcat[r] = rel_merge[r].ar[0:100] + rel_tri[r].ar[100:200]
__global__ void k_srcat(const float* __restrict__ rm, const float* __restrict__ rt,
    const float* __restrict__ ar, float* __restrict__ outv, int n)
{
    int w = (blockIdx.x*blockDim.x + threadIdx.x) >> 5;
    if (w >= n) return;
    int lane = threadIdx.x & 31;
    float u = 0.f;
    for (int c = lane; c < RHID; c += 32)
        u += rm[(size_t)w*RHID+c]*ar[c] + rt[(size_t)w*RHID+c]*ar[RHID+c];
    #pragma unroll
    for (int o = 16; o; o >>= 1) u += __shfl_down_sync(0xffffffffu, u, o);
    if (lane == 0) outv[w] = u;
}
__global__ void k_segmax(const float* __restrict__ v, const int* __restrict__ idx,
    unsigned* __restrict__ umax, int E)
{
    int i = blockIdx.x*blockDim.x + threadIdx.x;
    if (i < E) atomicMax(&umax[idx[i]], f2o(v[i]));
}
__global__ void k_segexp(const float* __restrict__ v, const int* __restrict__ idx,
    const unsigned* __restrict__ umax, float* __restrict__ p, float* __restrict__ sums, int E)
{
    int i = blockIdx.x*blockDim.x + threadIdx.x;
    if (i < E){
        int s = idx[i];
        float pv = expf(v[i] - o2f(umax[s]));
        p[i] = pv;
        atomicAdd(&sums[s], pv);
    }
}
__global__ void k_segnorm(float* __restrict__ p, const int* __restrict__ idx,
    const float* __restrict__ sums, int E)
{
    int i = blockIdx.x*blockDim.x + threadIdx.x;
    if (i < E) p[i] = p[i] / (sums[idx[i]] + 1e-16f);
}
__global__ void k_add(const float* __restrict__ a, const float* __restrict__ b,
    float* __restrict__ c, int n)
{
    int i = blockIdx.x*blockDim.x + threadIdx.x;
    if (i < n) c[i] = a[i] + b[i];
}
__global__ void k_relu(float* p, int n){
    int i = blockIdx.x*blockDim.x + threadIdx.x;
    if (i < n) p[i] = fmaxf(p[i], 0.f);
}
__global__ void k_relu_strided(float* p, int n, int d, int stride, int off){
    int i = blockIdx.x*blockDim.x + threadIdx.x;
    if (i < n*d){
        int r = i / d, c = i - r*d;
        float* q = p + (size_t)r*stride + off + c;
        *q = fmaxf(*q, 0.f);
    }
}
// GAT edge logit: e = leaky(si[i]+sj[j]+sr[rel mod R]); also seg-max by i
__global__ void k_gat_e(const int* __restrict__ ej, const int* __restrict__ ei,
    const int* __restrict__ rel, const float* __restrict__ si, const float* __restrict__ sj,
    const float* __restrict__ sr, float* __restrict__ eout, unsigned* __restrict__ umax, int E)
{
    int k = blockIdx.x*blockDim.x + threadIdx.x;
    if (k >= E) return;
    int j = ej[k], i = ei[k], r = rel[k];
    if (r >= RR) r -= RR;     // rel_emb rows are duplicated [rel_cat; rel_cat]
    float e = si[i] + sj[j] + sr[r];
    e = e > 0.f ? e : 0.01f*e;
    eout[k] = e;
    atomicMax(&umax[i], f2o(e));
}
// g2e edge logit: e = leaky(sn[node]+tr[rel]); seg-max by node
__global__ void k_g2e_e(const int* __restrict__ node, const int* __restrict__ rel,
    const float* __restrict__ sn, const float* __restrict__ tr,
    float* __restrict__ eout, unsigned* __restrict__ umax, int E)
{
    int k = blockIdx.x*blockDim.x + threadIdx.x;
    if (k >= E) return;
    int nd = node[k], r = rel[k];
    float e = sn[nd] + tr[r];
    e = e > 0.f ? e : 0.01f*e;
    eout[k] = e;
    atomicMax(&umax[nd], f2o(e));
}
// generic weighted scatter: out[idst[e]*ostride+ooff + d] += alpha[e]*x[jsrc[e]*xstride + d]
__global__ void k_scatter_alpha(const float* __restrict__ x, int xstride, int Dd,
    const int* __restrict__ jsrc, const int* __restrict__ idst,
    const float* __restrict__ alpha, float* __restrict__ out, int ostride, int ooff, int E)
{
    int w = (blockIdx.x*blockDim.x + threadIdx.x) >> 5;
    if (w >= E) return;
    int lane = threadIdx.x & 31;
    int j = __ldg(&jsrc[w]), i = __ldg(&idst[w]);
    float a = alpha[w];
    const float* src = x + (size_t)j*xstride;
    float* dst = out + (size_t)i*ostride + ooff;
    for (int d = lane; d < Dd; d += 32) atomicAdd(&dst[d], a * src[d]);
}

static inline int cdiv(int a, int b){ return (a + b - 1) / b; }

extern "C" void kernel_launch(void* const* d_in, const int* in_sizes, int n_in,
                              void* d_out, int out_size)
{
    const float* x_e      = (const float*)d_in[0];
    const float* mval     = (const float*)d_in[1];
    const float* tval     = (const float*)d_in[2];
    const float* gcn1_w   = (const float*)d_in[3];
    const float* hw1_w    = (const float*)d_in[4];
    const float* hw1_b    = (const float*)d_in[5];
    const float* gcn2_w   = (const float*)d_in[6];
    const float* hw2_w    = (const float*)d_in[7];
    const float* hw2_b    = (const float*)d_in[8];
    const float* rel_out1 = (const float*)d_in[9];
    const float* rel_tri1 = (const float*)d_in[10];
    const float* hwr_w    = (const float*)d_in[11];
    const float* hwr_b    = (const float*)d_in[12];
    const float* gat_ai   = (const float*)d_in[13];
    const float* gat_aj   = (const float*)d_in[14];
    const float* gat_ar   = (const float*)d_in[15];
    const float* g2e_ah   = (const float*)d_in[16];
    const float* g2e_at   = (const float*)d_in[17];
    const float* g2e_ar   = (const float*)d_in[18];
    const int*   ei_kg    = (const int*)d_in[19];
    const int*   rel_kg   = (const int*)d_in[20];
    const int*   ei_all   = (const int*)d_in[21];
    const int*   rel_all  = (const int*)d_in[22];
    const int*   lg_m     = (const int*)d_in[23];
    const int*   lg_t     = (const int*)d_in[24];
    float* out = (float*)d_out;

    const int* eall_j = ei_all;         const int* eall_i = ei_all + EAll;
    const int* ekg_h  = ei_kg;          const int* ekg_t  = ei_kg + EKG;
    const int* lgm_j  = lg_m;           const int* lgm_i  = lg_m + NLGE;
    const int* lgt_j  = lg_t;           const int* lgt_i  = lg_t + NLGE;

    float *pA,*pB,*pC,*pdeg,*pdinv,*ps1,*ps2,*psum,*peE,*peP;
    float *prm,*prt,*pxr,*prg,*plv1,*plv2,*plw,*prsum,*psrcat,*ptr_;
    unsigned *pumax, *prumax;
    cudaGetSymbolAddress((void**)&pA,    g_A);
    cudaGetSymbolAddress((void**)&pB,    g_B);
    cudaGetSymbolAddress((void**)&pC,    g_C);
    cudaGetSymbolAddress((void**)&pdeg,  g_deg);
    cudaGetSymbolAddress((void**)&pdinv, g_dinv);
    cudaGetSymbolAddress((void**)&ps1,   g_s1);
    cudaGetSymbolAddress((void**)&ps2,   g_s2);
    cudaGetSymbolAddress((void**)&pumax, g_umax);
    cudaGetSymbolAddress((void**)&psum,  g_sum);
    cudaGetSymbolAddress((void**)&peE,   g_eE);
    cudaGetSymbolAddress((void**)&peP,   g_eP);
    cudaGetSymbolAddress((void**)&prm,   g_rm);
    cudaGetSymbolAddress((void**)&prt,   g_rt);
    cudaGetSymbolAddress((void**)&pxr,   g_xr);
    cudaGetSymbolAddress((void**)&prg,   g_rg);
    cudaGetSymbolAddress((void**)&plv1,  g_lv1);
    cudaGetSymbolAddress((void**)&plv2,  g_lv2);
    cudaGetSymbolAddress((void**)&plw,   g_lw);
    cudaGetSymbolAddress((void**)&prumax,g_rumax);
    cudaGetSymbolAddress((void**)&prsum, g_rsum);
    cudaGetSymbolAddress((void**)&psrcat,g_srcat);
    cudaGetSymbolAddress((void**)&ptr_,  g_tr);

    const unsigned NEGINF = 0x007FFFFFu;   // f2o(-inf)

    // ---- degrees (in-degree over symmetric all-edge graph) ----
    cudaMemsetAsync(pdeg, 0, NN*sizeof(float), 0);
    k_deg<<<cdiv(EAll,256),256>>>(eall_i, pdeg, EAll);
    k_dinv<<<cdiv(NN,256),256>>>(pdeg, pdinv, NN);

    dim3 gemm_grid(cdiv(DH,128), cdiv(NN,128));

    // ---- GCN layer 1 + highway ----
    sgemm_nt<<<gemm_grid,256>>>(x_e, gcn1_w, pB, NN, DH, DH);
    cudaMemsetAsync(pC, 0, (size_t)NN*DH*sizeof(float), 0);
    k_gcn_scatter<<<cdiv(EAll*32,256),256>>>(pB, eall_j, eall_i, pdinv, pC, EAll);
    sgemm_nt<<<gemm_grid,256>>>(x_e, hw1_w, pB, NN, DH, DH);
    k_highway<<<cdiv(NN*DH,256),256>>>(x_e, pC, pB, hw1_b, pA, NN, DH, DH);

    // ---- GCN layer 2 + highway (writes x2 into out[:,0:300]) ----
    sgemm_nt<<<gemm_grid,256>>>(pA, gcn2_w, pB, NN, DH, DH);
    cudaMemsetAsync(pC, 0, (size_t)NN*DH*sizeof(float), 0);
    k_gcn_scatter<<<cdiv(EAll*32,256),256>>>(pB, eall_j, eall_i, pdinv, pC, EAll);
    sgemm_nt<<<gemm_grid,256>>>(pA, hw2_w, pB, NN, DH, DH);
    cudaMemsetAsync(out, 0, (size_t)NN*OSTR*sizeof(float), 0);
    k_highway<<<cdiv(NN*DH,256),256>>>(pA, pC, pB, hw2_b, out, NN, DH, OSTR);

    // ---- line-graph GATs over relations ----
    auto segsoftmax = [&](const float* vals, const int* idx, float* p, int E,
                          unsigned* um, float* sm, int nseg){
        k_fill_u32<<<cdiv(nseg,256),256>>>(um, NEGINF, nseg);
        k_segmax<<<cdiv(E,256),256>>>(vals, idx, um, E);
        cudaMemsetAsync(sm, 0, (size_t)nseg*sizeof(float), 0);
        k_segexp<<<cdiv(E,256),256>>>(vals, idx, um, p, sm, E);
        k_segnorm<<<cdiv(E,256),256>>>(p, idx, sm, E);
    };
    auto lgat = [&](const float* x0, const int* jj, const int* ii, const float* val, float* ob){
        segsoftmax(val, ii, plv1, NLGE, prumax, prsum, RR);   // vi (by dest)
        segsoftmax(val, jj, plv2, NLGE, prumax, prsum, RR);   // vj (by src)
        k_add<<<cdiv(NLGE,256),256>>>(plv1, plv2, plw, NLGE);
        segsoftmax(plw, jj, plw, NLGE, prumax, prsum, RR);    // alpha (by src!)
        cudaMemsetAsync(ob, 0, (size_t)RR*RHID*sizeof(float), 0);
        k_scatter_alpha<<<cdiv(NLGE*32,256),256>>>(x0, RHID, RHID, jj, ii, plw, ob, RHID, 0, NLGE);
        k_relu<<<cdiv(RR*RHID,256),256>>>(ob, RR*RHID);
    };
    lgat(rel_out1, lgm_j, lgm_i, mval, prm);   // rel_merge
    lgat(rel_tri1, lgt_j, lgt_i, tval, prt);   // rel_tri

    // ---- relation highway: x_r = g*rel_tri + (1-g)*rel_merge ----
    dim3 relgrid(cdiv(RHID,128), cdiv(RR,128));
    sgemm_nt<<<relgrid,256>>>(prm, hwr_w, prg, RR, RHID, RHID);
    k_highway<<<cdiv(RR*RHID,256),256>>>(prm, prt, prg, hwr_b, pxr, RR, RHID, RHID);
    // (rel_tri >= 0 already, so the relu inside k_highway is a no-op — exact)

    // ---- GAT on all-edge graph: out[:,300:600] ----
    k_dot2<<<cdiv(NN*32,256),256>>>(out, OSTR, DH, gat_ai, gat_aj, ps1, ps2, NN);
    k_srcat<<<cdiv(RR*32,256),256>>>(prm, prt, gat_ar, psrcat, RR);
    k_fill_u32<<<cdiv(NN,256),256>>>(pumax, NEGINF, NN);
    k_gat_e<<<cdiv(EAll,256),256>>>(eall_j, eall_i, rel_all, ps1, ps2, psrcat, peE, pumax, EAll);
    cudaMemsetAsync(psum, 0, NN*sizeof(float), 0);
    k_segexp<<<cdiv(EAll,256),256>>>(peE, eall_i, pumax, peP, psum, EAll);
    k_segnorm<<<cdiv(EAll,256),256>>>(peP, eall_i, psum, EAll);
    k_scatter_alpha<<<cdiv(EAll*32,256),256>>>(out, OSTR, DH, eall_j, eall_i, peP, out, OSTR, DH, EAll);
    k_relu_strided<<<cdiv(NN*DH,256),256>>>(out, NN, DH, OSTR, DH);

    // ---- gat_r_to_e: out[:,600:700] (by head) and out[:,700:800] (by tail) ----
    k_dot2<<<cdiv(NN*32,256),256>>>(out, OSTR, 600, g2e_ah, g2e_at, ps1, ps2, NN);   // eh, et
    k_dot2<<<cdiv(RR*32,256),256>>>(pxr, RHID, RHID, g2e_ar, g2e_ar, ptr_, (float*)0, RR); // t_r
    // a1 by h
    k_fill_u32<<<cdiv(NN,256),256>>>(pumax, NEGINF, NN);
    k_g2e_e<<<cdiv(EKG,256),256>>>(ekg_h, rel_kg, ps1, ptr_, peE, pumax, EKG);
    cudaMemsetAsync(psum, 0, NN*sizeof(float), 0);
    k_segexp<<<cdiv(EKG,256),256>>>(peE, ekg_h, pumax, peP, psum, EKG);
    k_segnorm<<<cdiv(EKG,256),256>>>(peP, ekg_h, psum, EKG);
    k_scatter_alpha<<<cdiv(EKG*32,256),256>>>(pxr, RHID, RHID, rel_kg, ekg_h, peP, out, OSTR, 600, EKG);
    // a2 by t
    k_fill_u32<<<cdiv(NN,256),256>>>(pumax, NEGINF, NN);
    k_g2e_e<<<cdiv(EKG,256),256>>>(ekg_t, rel_kg, ps2, ptr_, peE, pumax, EKG);
    cudaMemsetAsync(psum, 0, NN*sizeof(float), 0);
    k_segexp<<<cdiv(EKG,256),256>>>(peE, ekg_t, pumax, peP, psum, EKG);
    k_segnorm<<<cdiv(EKG,256),256>>>(peP, ekg_t, psum, EKG);
    k_scatter_alpha<<<cdiv(EKG*32,256),256>>>(pxr, RHID, RHID, rel_kg, ekg_t, peP, out, OSTR, 700, EKG);
}

// round 2
// speedup vs baseline: 1.3096x; 1.3096x over previous
#include <cuda_runtime.h>

// Problem constants (fixed by the reference)
#define NN    100000   // entities
#define DH    300      // e_hidden
#define EAll  800000   // symmetric all-edge count (2*EH)
#define EKG   400000   // KG1 triples
#define RR    2000     // relations
#define RHID  100      // r_hidden
#define NLGE  60000    // line-graph edges
#define OSTR  800      // output row stride
#define SCAN_BLK 1024

// ------------------------- scratch (static, allocation-free) -------------------------
__device__ float    g_A[(size_t)NN*DH];
__device__ float    g_B[(size_t)NN*DH];
__device__ float    g_C[(size_t)NN*DH];
__device__ float    g_dinv[NN];
__device__ float    g_s1[NN];
__device__ float    g_s2[NN];

__device__ int      g_cnt[NN];
__device__ int      g_rowA[NN+1];
__device__ int      g_rowH[NN+1];
__device__ int      g_rowT[NN+1];
__device__ int      g_cur[NN];
__device__ int      g_permA[EAll];
__device__ int      g_permH[EKG];
__device__ int      g_permT[EKG];
__device__ int      g_scantmp[NN];
__device__ int      g_bsum[1024];

__device__ float    g_rm[RR*RHID];
__device__ float    g_rt[RR*RHID];
__device__ float    g_xr[RR*RHID];
__device__ float    g_rg[RR*RHID];
__device__ float    g_lv1[NLGE];
__device__ float    g_lv2[NLGE];
__device__ float    g_lw[NLGE];
__device__ unsigned g_rumax[RR];
__device__ float    g_rsum[RR];
__device__ float    g_srcat[RR];
__device__ float    g_tr[RR];

// Order-preserving float <-> uint mapping (atomicMax on floats)
__device__ __forceinline__ unsigned f2o(float f){
    unsigned u = __float_as_uint(f);
    return (u & 0x80000000u) ? ~u : (u | 0x80000000u);
}
__device__ __forceinline__ float o2f(unsigned u){
    return (u & 0x80000000u) ? __uint_as_float(u & 0x7fffffffu) : __uint_as_float(~u);
}

// ------------------------- GEMM: C[M,N] = A[M,K] * B[N,K]^T -------------------------
__global__ __launch_bounds__(256) void sgemm_nt(
    const float* __restrict__ A, const float* __restrict__ B,
    float* __restrict__ C, int M, int N, int K)
{
    __shared__ float As[8][128];
    __shared__ float Bs[8][128];
    int bm = blockIdx.y * 128;
    int bn = blockIdx.x * 128;
    int tid = threadIdx.x;
    int tx = tid & 15;
    int ty = tid >> 4;
    int lrow = tid >> 1;
    int lcol = (tid & 1) * 4;

    float acc[8][8];
    #pragma unroll
    for (int i = 0; i < 8; i++)
        #pragma unroll
        for (int j = 0; j < 8; j++) acc[i][j] = 0.f;

    for (int k0 = 0; k0 < K; k0 += 8) {
        float4 av = make_float4(0.f,0.f,0.f,0.f);
        float4 bv = make_float4(0.f,0.f,0.f,0.f);
        int gk = k0 + lcol;
        int ar = bm + lrow;
        if (ar < M) {
            if (gk + 4 <= K) av = *reinterpret_cast<const float4*>(A + (size_t)ar*K + gk);
            else {
                float* p = reinterpret_cast<float*>(&av);
                for (int u = 0; u < 4; u++) if (gk + u < K) p[u] = A[(size_t)ar*K + gk + u];
            }
        }
        int br = bn + lrow;
        if (br < N) {
            if (gk + 4 <= K) bv = *reinterpret_cast<const float4*>(B + (size_t)br*K + gk);
            else {
                float* p = reinterpret_cast<float*>(&bv);
                for (int u = 0; u < 4; u++) if (gk + u < K) p[u] = B[(size_t)br*K + gk + u];
            }
        }
        As[lcol+0][lrow]=av.x; As[lcol+1][lrow]=av.y; As[lcol+2][lrow]=av.z; As[lcol+3][lrow]=av.w;
        Bs[lcol+0][lrow]=bv.x; Bs[lcol+1][lrow]=bv.y; Bs[lcol+2][lrow]=bv.z; Bs[lcol+3][lrow]=bv.w;
        __syncthreads();
        #pragma unroll
        for (int kk = 0; kk < 8; kk++) {
            float a[8], b[8];
            #pragma unroll
            for (int i = 0; i < 8; i++) a[i] = As[kk][ty*8+i];
            #pragma unroll
            for (int j = 0; j < 8; j++) b[j] = Bs[kk][tx*8+j];
            #pragma unroll
            for (int i = 0; i < 8; i++)
                #pragma unroll
                for (int j = 0; j < 8; j++) acc[i][j] = fmaf(a[i], b[j], acc[i][j]);
        }
        __syncthreads();
    }
    #pragma unroll
    for (int i = 0; i < 8; i++) {
        int r = bm + ty*8 + i;
        if (r >= M) continue;
        #pragma unroll
        for (int j = 0; j < 8; j++) {
            int c = bn + tx*8 + j;
            if (c < N) C[(size_t)r*N + c] = acc[i][j];
        }
    }
}

// ------------------------- CSR construction -------------------------
__global__ void k_hist(const int* __restrict__ idx, int* __restrict__ cnt, int E){
    int i = blockIdx.x*blockDim.x + threadIdx.x;
    if (i < E) atomicAdd(&cnt[idx[i]], 1);
}
__global__ void k_scan_block(const int* __restrict__ in, int* __restrict__ out,
                             int* __restrict__ bsum, int n){
    __shared__ int sh[SCAN_BLK];
    int t = threadIdx.x;
    int g = blockIdx.x*SCAN_BLK + t;
    int v = (g < n) ? in[g] : 0;
    sh[t] = v; __syncthreads();
    for (int off = 1; off < SCAN_BLK; off <<= 1){
        int x = 0; if (t >= off) x = sh[t-off];
        __syncthreads();
        sh[t] += x;
        __syncthreads();
    }
    if (g < n) out[g] = sh[t];
    if (t == SCAN_BLK-1) bsum[blockIdx.x] = sh[t];
}
__global__ void k_scan_partials(int* __restrict__ bsum, int nb){
    __shared__ int sh[1024];
    int t = threadIdx.x;
    int v = (t < nb) ? bsum[t] : 0;
    sh[t] = v; __syncthreads();
    for (int off = 1; off < 1024; off <<= 1){
        int x = 0; if (t >= off) x = sh[t-off];
        __syncthreads();
        sh[t] += x;
        __syncthreads();
    }
    if (t < nb) bsum[t] = sh[t] - v;   // exclusive
}
__global__ void k_scan_final(const int* __restrict__ tmp, const int* __restrict__ bsum,
                             int* __restrict__ row_ptr, int n){
    int g = blockIdx.x*blockDim.x + threadIdx.x;
    if (g < n) row_ptr[g+1] = tmp[g] + bsum[g/SCAN_BLK];
    if (g == 0) row_ptr[0] = 0;
}
__global__ void k_permute(const int* __restrict__ idx, int* __restrict__ cursor,
                          int* __restrict__ perm, int E){
    int i = blockIdx.x*blockDim.x + threadIdx.x;
    if (i < E){
        int pos = atomicAdd(&cursor[idx[i]], 1);
        perm[pos] = i;
    }
}
__global__ void k_dinv_cnt(const int* __restrict__ cnt, float* __restrict__ dinv, int n){
    int i = blockIdx.x*blockDim.x + threadIdx.x;
    if (i < n){ int d = cnt[i]; dinv[i] = d > 0 ? rsqrtf((float)d) : 0.f; }
}

// ------------------------- fused per-node gathers -------------------------
// GCN: out[i] = sum_e dinv[j]*dinv[i]*xw[j]; warp per node; 300 dims = 75 float4
__global__ __launch_bounds__(256) void k_gcn_gather(
    const float* __restrict__ xw, const int* __restrict__ ej,
    const int* __restrict__ row, const int* __restrict__ perm,
    const float* __restrict__ dinv, float* __restrict__ outp, int n)
{
    int w = (blockIdx.x*blockDim.x + threadIdx.x) >> 5;
    if (w >= n) return;
    int lane = threadIdx.x & 31;
    int s = row[w], e = row[w+1];
    float di = dinv[w];
    float4 acc[3];
    #pragma unroll
    for (int u = 0; u < 3; u++) acc[u] = make_float4(0.f,0.f,0.f,0.f);
    for (int k = s; k < e; k++){
        int eid = perm[k];
        int j = __ldg(&ej[eid]);
        float nrm = di * __ldg(&dinv[j]);
        const float4* src = reinterpret_cast<const float4*>(xw + (size_t)j*DH);
        #pragma unroll
        for (int u = 0; u < 3; u++){
            int v = lane + u*32;
            if (v < DH/4){
                float4 sv = __ldg(&src[v]);
                acc[u].x = fmaf(nrm, sv.x, acc[u].x);
                acc[u].y = fmaf(nrm, sv.y, acc[u].y);
                acc[u].z = fmaf(nrm, sv.z, acc[u].z);
                acc[u].w = fmaf(nrm, sv.w, acc[u].w);
            }
        }
    }
    float4* dst = reinterpret_cast<float4*>(outp + (size_t)w*DH);
    #pragma unroll
    for (int u = 0; u < 3; u++){
        int v = lane + u*32;
        if (v < DH/4) dst[v] = acc[u];
    }
}

// GAT fused: logits+softmax+aggregate per dest node. x rows at stride OSTR (cols 0..299),
// output to out[:,300:600] with relu.
__global__ __launch_bounds__(256) void k_gat_fused(
    const float* __restrict__ x, const int* __restrict__ ej, const int* __restrict__ rel,
    const int* __restrict__ row, const int* __restrict__ perm,
    const float* __restrict__ si, const float* __restrict__ sj, const float* __restrict__ sr,
    float* __restrict__ outp, int n)
{
    int w = (blockIdx.x*blockDim.x + threadIdx.x) >> 5;
    if (w >= n) return;
    int lane = threadIdx.x & 31;
    int s = row[w], e = row[w+1];
    float4 acc[3];
    #pragma unroll
    for (int u = 0; u < 3; u++) acc[u] = make_float4(0.f,0.f,0.f,0.f);
    if (s < e){
        float svi = si[w];
        float m = -1e30f;
        for (int k = s + lane; k < e; k += 32){
            int eid = perm[k];
            int j = __ldg(&ej[eid]);
            int r = __ldg(&rel[eid]); if (r >= RR) r -= RR;
            float t = svi + __ldg(&sj[j]) + __ldg(&sr[r]);
            t = t > 0.f ? t : 0.01f*t;
            m = fmaxf(m, t);
        }
        #pragma unroll
        for (int o = 16; o; o >>= 1) m = fmaxf(m, __shfl_xor_sync(0xffffffffu, m, o));
        float ssum = 0.f;
        for (int k = s + lane; k < e; k += 32){
            int eid = perm[k];
            int j = __ldg(&ej[eid]);
            int r = __ldg(&rel[eid]); if (r >= RR) r -= RR;
            float t = svi + __ldg(&sj[j]) + __ldg(&sr[r]);
            t = t > 0.f ? t : 0.01f*t;
            ssum += expf(t - m);
        }
        #pragma unroll
        for (int o = 16; o; o >>= 1) ssum += __shfl_xor_sync(0xffffffffu, ssum, o);
        float inv = 1.f / (ssum + 1e-16f);
        for (int k = s; k < e; k++){
            int eid = perm[k];
            int j = __ldg(&ej[eid]);
            int r = __ldg(&rel[eid]); if (r >= RR) r -= RR;
            float t = svi + __ldg(&sj[j]) + __ldg(&sr[r]);
            t = t > 0.f ? t : 0.01f*t;
            float a = expf(t - m) * inv;
            const float4* src = reinterpret_cast<const float4*>(x + (size_t)j*OSTR);
            #pragma unroll
            for (int u = 0; u < 3; u++){
                int v = lane + u*32;
                if (v < DH/4){
                    float4 sv = __ldg(&src[v]);
                    acc[u].x = fmaf(a, sv.x, acc[u].x);
                    acc[u].y = fmaf(a, sv.y, acc[u].y);
                    acc[u].z = fmaf(a, sv.z, acc[u].z);
                    acc[u].w = fmaf(a, sv.w, acc[u].w);
                }
            }
        }
    }
    float4* dst = reinterpret_cast<float4*>(outp + (size_t)w*OSTR + DH);
    #pragma unroll
    for (int u = 0; u < 3; u++){
        int v = lane + u*32;
        if (v < DH/4){
            float4 av = acc[u];
            av.x = fmaxf(av.x, 0.f); av.y = fmaxf(av.y, 0.f);
            av.z = fmaxf(av.z, 0.f); av.w = fmaxf(av.w, 0.f);
            dst[v] = av;
        }
    }
}

// g2e fused: per-node softmax over leaky(sn[node]+tr[rel]) and aggregate x_r[rel] (100-dim).
__global__ __launch_bounds__(256) void k_g2e_fused(
    const float* __restrict__ xr, const int* __restrict__ rel,
    const int* __restrict__ row, const int* __restrict__ perm,
    const float* __restrict__ sn, const float* __restrict__ tr,
    float* __restrict__ outp, int ooff, int n)
{
    int w = (blockIdx.x*blockDim.x + threadIdx.x) >> 5;
    if (w >= n) return;
    int lane = threadIdx.x & 31;
    int s = row[w], e = row[w+1];
    float4 acc = make_float4(0.f,0.f,0.f,0.f);
    if (s < e){
        float svn = sn[w];
        float m = -1e30f;
        for (int k = s + lane; k < e; k += 32){
            int r = __ldg(&rel[perm[k]]);
            float t = svn + __ldg(&tr[r]);
            t = t > 0.f ? t : 0.01f*t;
            m = fmaxf(m, t);
        }
        #pragma unroll
        for (int o = 16; o; o >>= 1) m = fmaxf(m, __shfl_xor_sync(0xffffffffu, m, o));
        float ssum = 0.f;
        for (int k = s + lane; k < e; k += 32){
            int r = __ldg(&rel[perm[k]]);
            float t = svn + __ldg(&tr[r]);
            t = t > 0.f ? t : 0.01f*t;
            ssum += expf(t - m);
        }
        #pragma unroll
        for (int o = 16; o; o >>= 1) ssum += __shfl_xor_sync(0xffffffffu, ssum, o);
        float inv = 1.f / (ssum + 1e-16f);
        for (int k = s; k < e; k++){
            int r = __ldg(&rel[perm[k]]);
            float t = svn + __ldg(&tr[r]);
            t = t > 0.f ? t : 0.01f*t;
            float a = expf(t - m) * inv;
            if (lane < RHID/4){
                const float4* src = reinterpret_cast<const float4*>(xr + (size_t)r*RHID);
                float4 sv = __ldg(&src[lane]);
                acc.x = fmaf(a, sv.x, acc.x);
                acc.y = fmaf(a, sv.y, acc.y);
                acc.z = fmaf(a, sv.z, acc.z);
                acc.w = fmaf(a, sv.w, acc.w);
            }
        }
    }
    if (lane < RHID/4)
        reinterpret_cast<float4*>(outp + (size_t)w*OSTR + ooff)[lane] = acc;
}

// ------------------------- elementwise / small-graph kernels -------------------------
__global__ void k_fill_u32(unsigned* p, unsigned v, int n){
    int i = blockIdx.x*blockDim.x + threadIdx.x;
    if (i < n) p[i] = v;
}
__global__ void k_highway(const float* __restrict__ x, const float* __restrict__ sc,
    const float* __restrict__ G, const float* __restrict__ b,
    float* __restrict__ out, int n, int d, int ostride)
{
    int idx = blockIdx.x*blockDim.x + threadIdx.x;
    if (idx >= n*d) return;
    int r = idx / d, c = idx - r*d;
    float x2 = fmaxf(sc[idx], 0.f);
    float g = 1.f / (1.f + expf(-(G[idx] + b[c])));
    out[(size_t)r*ostride + c] = g*x2 + (1.f - g)*x[idx];
}
__global__ void k_dot2(const float* __restrict__ x, int ld, int d,
    const float* __restrict__ a1, const float* __restrict__ a2,
    float* __restrict__ s1, float* __restrict__ s2, int n)
{
    int w = (blockIdx.x*blockDim.x + threadIdx.x) >> 5;
    if (w >= n) return;
    int lane = threadIdx.x & 31;
    const float* row = x + (size_t)w*ld;
    float u = 0.f, v = 0.f;
    for (int c = lane; c < d; c += 32){ float xv = row[c]; u += xv*a1[c]; v += xv*a2[c]; }
    #pragma unroll
    for (int o = 16; o; o >>= 1){
        u += __shfl_down_sync(0xffffffffu, u, o);
        v += __shfl_down_sync(0xffffffffu, v, o);
    }
    if (lane == 0){ s1[w] = u; if (s2) s2[w] = v; }
}
__global__ void k_srcat(const float* __restrict__ rm, const float* __restrict__ rt,
    const float* __restrict__ ar, float* __restrict__ outv, int n)
{
    int w = (blockIdx.x*blockDim.x + threadIdx.x) >> 5;
    if (w >= n) return;
    int lane = threadIdx.x & 31;
    float u = 0.f;
    for (int c = lane; c < RHID; c += 32)
        u += rm[(size_t)w*RHID+c]*ar[c] + rt[(size_t)w*RHID+c]*ar[RHID+c];
    #pragma unroll
    for (int o = 16; o; o >>= 1) u += __shfl_down_sync(0xffffffffu, u, o);
    if (lane == 0) outv[w] = u;
}
__global__ void k_segmax(const float* __restrict__ v, const int* __restrict__ idx,
    unsigned* __restrict__ umax, int E)
{
    int i = blockIdx.x*blockDim.x + threadIdx.x;
    if (i < E) atomicMax(&umax[idx[i]], f2o(v[i]));
}
__global__ void k_segexp(const float* __restrict__ v, const int* __restrict__ idx,
    const unsigned* __restrict__ umax, float* __restrict__ p, float* __restrict__ sums, int E)
{
    int i = blockIdx.x*blockDim.x + threadIdx.x;
    if (i < E){
        int s = idx[i];
        float pv = expf(v[i] - o2f(umax[s]));
        p[i] = pv;
        atomicAdd(&sums[s], pv);
    }
}
__global__ void k_segnorm(float* __restrict__ p, const int* __restrict__ idx,
    const float* __restrict__ sums, int E)
{
    int i = blockIdx.x*blockDim.x + threadIdx.x;
    if (i < E) p[i] = p[i] / (sums[idx[i]] + 1e-16f);
}
__global__ void k_add(const float* __restrict__ a, const float* __restrict__ b,
    float* __restrict__ c, int n)
{
    int i = blockIdx.x*blockDim.x + threadIdx.x;
    if (i < n) c[i] = a[i] + b[i];
}
__global__ void k_relu(float* p, int n){
    int i = blockIdx.x*blockDim.x + threadIdx.x;
    if (i < n) p[i] = fmaxf(p[i], 0.f);
}
__global__ void k_scatter_alpha(const float* __restrict__ x, int xstride, int Dd,
    const int* __restrict__ jsrc, const int* __restrict__ idst,
    const float* __restrict__ alpha, float* __restrict__ out, int ostride, int ooff, int E)
{
    int w = (blockIdx.x*blockDim.x + threadIdx.x) >> 5;
    if (w >= E) return;
    int lane = threadIdx.x & 31;
    int j = __ldg(&jsrc[w]), i = __ldg(&idst[w]);
    float a = alpha[w];
    const float* src = x + (size_t)j*xstride;
    float* dst = out + (size_t)i*ostride + ooff;
    for (int d = lane; d < Dd; d += 32) atomicAdd(&dst[d], a * src[d]);
}

static inline int cdiv(int a, int b){ return (a + b - 1) / b; }

extern "C" void kernel_launch(void* const* d_in, const int* in_sizes, int n_in,
                              void* d_out, int out_size)
{
    const float* x_e      = (const float*)d_in[0];
    const float* mval     = (const float*)d_in[1];
    const float* tval     = (const float*)d_in[2];
    const float* gcn1_w   = (const float*)d_in[3];
    const float* hw1_w    = (const float*)d_in[4];
    const float* hw1_b    = (const float*)d_in[5];
    const float* gcn2_w   = (const float*)d_in[6];
    const float* hw2_w    = (const float*)d_in[7];
    const float* hw2_b    = (const float*)d_in[8];
    const float* rel_out1 = (const float*)d_in[9];
    const float* rel_tri1 = (const float*)d_in[10];
    const float* hwr_w    = (const float*)d_in[11];
    const float* hwr_b    = (const float*)d_in[12];
    const float* gat_ai   = (const float*)d_in[13];
    const float* gat_aj   = (const float*)d_in[14];
    const float* gat_ar   = (const float*)d_in[15];
    const float* g2e_ah   = (const float*)d_in[16];
    const float* g2e_at   = (const float*)d_in[17];
    const float* g2e_ar   = (const float*)d_in[18];
    const int*   ei_kg    = (const int*)d_in[19];
    const int*   rel_kg   = (const int*)d_in[20];
    const int*   ei_all   = (const int*)d_in[21];
    const int*   rel_all  = (const int*)d_in[22];
    const int*   lg_m     = (const int*)d_in[23];
    const int*   lg_t     = (const int*)d_in[24];
    float* out = (float*)d_out;

    const int* eall_j = ei_all;         const int* eall_i = ei_all + EAll;
    const int* ekg_h  = ei_kg;          const int* ekg_t  = ei_kg + EKG;
    const int* lgm_j  = lg_m;           const int* lgm_i  = lg_m + NLGE;
    const int* lgt_j  = lg_t;           const int* lgt_i  = lg_t + NLGE;

    float *pA,*pB,*pC,*pdinv,*ps1,*ps2;
    float *prm,*prt,*pxr,*prg,*plv1,*plv2,*plw,*prsum,*psrcat,*ptr_;
    unsigned *prumax;
    int *pcnt,*prowA,*prowH,*prowT,*pcur,*ppermA,*ppermH,*ppermT,*pscantmp,*pbsum;
    cudaGetSymbolAddress((void**)&pA,    g_A);
    cudaGetSymbolAddress((void**)&pB,    g_B);
    cudaGetSymbolAddress((void**)&pC,    g_C);
    cudaGetSymbolAddress((void**)&pdinv, g_dinv);
    cudaGetSymbolAddress((void**)&ps1,   g_s1);
    cudaGetSymbolAddress((void**)&ps2,   g_s2);
    cudaGetSymbolAddress((void**)&prm,   g_rm);
    cudaGetSymbolAddress((void**)&prt,   g_rt);
    cudaGetSymbolAddress((void**)&pxr,   g_xr);
    cudaGetSymbolAddress((void**)&prg,   g_rg);
    cudaGetSymbolAddress((void**)&plv1,  g_lv1);
    cudaGetSymbolAddress((void**)&plv2,  g_lv2);
    cudaGetSymbolAddress((void**)&plw,   g_lw);
    cudaGetSymbolAddress((void**)&prumax,g_rumax);
    cudaGetSymbolAddress((void**)&prsum, g_rsum);
    cudaGetSymbolAddress((void**)&psrcat,g_srcat);
    cudaGetSymbolAddress((void**)&ptr_,  g_tr);
    cudaGetSymbolAddress((void**)&pcnt,  g_cnt);
    cudaGetSymbolAddress((void**)&prowA, g_rowA);
    cudaGetSymbolAddress((void**)&prowH, g_rowH);
    cudaGetSymbolAddress((void**)&prowT, g_rowT);
    cudaGetSymbolAddress((void**)&pcur,  g_cur);
    cudaGetSymbolAddress((void**)&ppermA,g_permA);
    cudaGetSymbolAddress((void**)&ppermH,g_permH);
    cudaGetSymbolAddress((void**)&ppermT,g_permT);
    cudaGetSymbolAddress((void**)&pscantmp, g_scantmp);
    cudaGetSymbolAddress((void**)&pbsum, g_bsum);

    const unsigned NEGINF = 0x007FFFFFu;   // f2o(-inf)
    const int nscanblk = cdiv(NN, SCAN_BLK);

    // ---- build CSR helper ----
    auto build_csr = [&](const int* idx, int E, int* row_ptr, int* perm){
        cudaMemsetAsync(pcnt, 0, NN*sizeof(int), 0);
        k_hist<<<cdiv(E,256),256>>>(idx, pcnt, E);
        k_scan_block<<<nscanblk, SCAN_BLK>>>(pcnt, pscantmp, pbsum, NN);
        k_scan_partials<<<1,1024>>>(pbsum, nscanblk);
        k_scan_final<<<cdiv(NN,256),256>>>(pscantmp, pbsum, row_ptr, NN);
        cudaMemcpyAsync(pcur, row_ptr, NN*sizeof(int), cudaMemcpyDeviceToDevice, 0);
        k_permute<<<cdiv(E,256),256>>>(idx, pcur, perm, E);
    };

    // CSR over all-edge graph by destination (also yields degrees -> dinv)
    build_csr(eall_i, EAll, prowA, ppermA);
    k_dinv_cnt<<<cdiv(NN,256),256>>>(pcnt, pdinv, NN);
    // CSRs over KG edges by head and tail
    build_csr(ekg_h, EKG, prowH, ppermH);
    build_csr(ekg_t, EKG, prowT, ppermT);

    dim3 gemm_grid(cdiv(DH,128), cdiv(NN,128));
    const int GW = cdiv(NN*32, 256);   // warp-per-node grids

    // ---- GCN layer 1 + highway ----
    sgemm_nt<<<gemm_grid,256>>>(x_e, gcn1_w, pB, NN, DH, DH);
    k_gcn_gather<<<GW,256>>>(pB, eall_j, prowA, ppermA, pdinv, pC, NN);
    sgemm_nt<<<gemm_grid,256>>>(x_e, hw1_w, pB, NN, DH, DH);
    k_highway<<<cdiv(NN*DH,256),256>>>(x_e, pC, pB, hw1_b, pA, NN, DH, DH);

    // ---- GCN layer 2 + highway (writes x2 into out[:,0:300]) ----
    sgemm_nt<<<gemm_grid,256>>>(pA, gcn2_w, pB, NN, DH, DH);
    k_gcn_gather<<<GW,256>>>(pB, eall_j, prowA, ppermA, pdinv, pC, NN);
    sgemm_nt<<<gemm_grid,256>>>(pA, hw2_w, pB, NN, DH, DH);
    k_highway<<<cdiv(NN*DH,256),256>>>(pA, pC, pB, hw2_b, out, NN, DH, OSTR);

    // ---- line-graph GATs over relations (small; atomic path) ----
    auto segsoftmax = [&](const float* vals, const int* idx, float* p, int E){
        k_fill_u32<<<cdiv(RR,256),256>>>(prumax, NEGINF, RR);
        k_segmax<<<cdiv(E,256),256>>>(vals, idx, prumax, E);
        cudaMemsetAsync(prsum, 0, RR*sizeof(float), 0);
        k_segexp<<<cdiv(E,256),256>>>(vals, idx, prumax, p, prsum, E);
        k_segnorm<<<cdiv(E,256),256>>>(p, idx, prsum, E);
    };
    auto lgat = [&](const float* x0, const int* jj, const int* ii, const float* val, float* ob){
        segsoftmax(val, ii, plv1, NLGE);
        segsoftmax(val, jj, plv2, NLGE);
        k_add<<<cdiv(NLGE,256),256>>>(plv1, plv2, plw, NLGE);
        segsoftmax(plw, jj, plw, NLGE);
        cudaMemsetAsync(ob, 0, (size_t)RR*RHID*sizeof(float), 0);
        k_scatter_alpha<<<cdiv(NLGE*32,256),256>>>(x0, RHID, RHID, jj, ii, plw, ob, RHID, 0, NLGE);
        k_relu<<<cdiv(RR*RHID,256),256>>>(ob, RR*RHID);
    };
    lgat(rel_out1, lgm_j, lgm_i, mval, prm);
    lgat(rel_tri1, lgt_j, lgt_i, tval, prt);

    // ---- relation highway ----
    dim3 relgrid(cdiv(RHID,128), cdiv(RR,128));
    sgemm_nt<<<relgrid,256>>>(prm, hwr_w, prg, RR, RHID, RHID);
    k_highway<<<cdiv(RR*RHID,256),256>>>(prm, prt, prg, hwr_b, pxr, RR, RHID, RHID);

    // ---- GAT on all-edge graph: out[:,300:600] (fused) ----
    k_dot2<<<cdiv(NN*32,256),256>>>(out, OSTR, DH, gat_ai, gat_aj, ps1, ps2, NN);
    k_srcat<<<cdiv(RR*32,256),256>>>(prm, prt, gat_ar, psrcat, RR);
    k_gat_fused<<<GW,256>>>(out, eall_j, rel_all, prowA, ppermA, ps1, ps2, psrcat, out, NN);

    // ---- gat_r_to_e: out[:,600:700] and out[:,700:800] (fused) ----
    k_dot2<<<cdiv(NN*32,256),256>>>(out, OSTR, 600, g2e_ah, g2e_at, ps1, ps2, NN);
    k_dot2<<<cdiv(RR*32,256),256>>>(pxr, RHID, RHID, g2e_ar, g2e_ar, ptr_, (float*)0, RR);
    k_g2e_fused<<<GW,256>>>(pxr, rel_kg, prowH, ppermH, ps1, ptr_, out, 600, NN);
    k_g2e_fused<<<GW,256>>>(pxr, rel_kg, prowT, ppermT, ps2, ptr_, out, 700, NN);
}